// round 8
// baseline (speedup 1.0000x reference)
#include <cuda_runtime.h>
#include <cuda_bf16.h>

// GNN_30064771072959: 2-layer GCN (DGL GraphConv, norm='both')
// R8: FFMA2 GEMM with zero inner-loop MOVs:
//   - row-pair packing: a = {A[r0][k], A[r1][k]} from transposed smem tile
//   - W pre-duplicated {w,w} into __device__ global by k_dupw, staged to smem
//   - scan2 merged into scan finalize

#define MAXN 131072
#define MAXE 1700000
#define SCAN_CHUNK 1024
#define MAXCHUNK (MAXN / SCAN_CHUNK)   // 128

typedef unsigned long long u64;

__device__ float g_x[MAXN * 128];      // GEMM output (gather source)
__device__ float g_h[MAXN * 128];      // layer-1 hidden
__device__ int   g_col[MAXE];          // CSR col (= src) by dst
__device__ int   g_rowptr[MAXN + 1];
__device__ int   g_cursor[MAXN];
__device__ int   g_degout[MAXN];
__device__ int   g_degin[MAXN];
__device__ float g_nsrc[MAXN];
__device__ float g_ndst[MAXN];
__device__ int   g_part[MAXCHUNK];
__device__ u64   g_W2[2][128 * 128];   // duplicated-pair weights {w,w}

__device__ __forceinline__ u64 fma2(u64 a, u64 b, u64 c) {
    u64 d;
    asm("fma.rn.f32x2 %0, %1, %2, %3;" : "=l"(d) : "l"(a), "l"(b), "l"(c));
    return d;
}

// ---------------------------------------------------------------- degrees
__global__ void k_zero(int n) {
    int i = blockIdx.x * blockDim.x + threadIdx.x;
    if (i < n) { g_degout[i] = 0; g_degin[i] = 0; }
}

__global__ void k_deg(const int* __restrict__ src, const int* __restrict__ dst, int E) {
    int e = blockIdx.x * blockDim.x + threadIdx.x;
    if (e < E) {
        atomicAdd(&g_degout[src[e]], 1);
        atomicAdd(&g_degin[dst[e]], 1);
    }
}

// ---------------------------------------------------------------- W duplication
__global__ void k_dupw(const float* __restrict__ W1, const float* __restrict__ W2) {
    int i = blockIdx.x * blockDim.x + threadIdx.x;
    if (i < 128 * 128) {
        unsigned int a = __float_as_uint(W1[i]);
        unsigned int b = __float_as_uint(W2[i]);
        g_W2[0][i] = ((u64)a << 32) | a;
        g_W2[1][i] = ((u64)b << 32) | b;
    }
}

// ---------------------------------------------------------------- scan (rowptr)
__global__ void k_scan1(int n) {
    __shared__ int s[SCAN_CHUNK];
    int t = threadIdx.x;
    int i = blockIdx.x * SCAN_CHUNK + t;
    int v = (i < n) ? g_degin[i] : 0;
    s[t] = v;
    __syncthreads();
    #pragma unroll
    for (int off = 1; off < SCAN_CHUNK; off <<= 1) {
        int add = (t >= off) ? s[t - off] : 0;
        __syncthreads();
        s[t] += add;
        __syncthreads();
    }
    if (i < n) g_rowptr[i] = s[t] - v;          // local exclusive
    if (t == SCAN_CHUNK - 1) g_part[blockIdx.x] = s[t];
}

// finalize: every block redundantly scans the (<=128) chunk partials in smem,
// then computes rowptr/cursor/norms. Replaces old k_scan2 + k_scan3.
__global__ void k_scanfin(int n, int E, int nchunk) {
    __shared__ int s[MAXCHUNK];
    int t = threadIdx.x;
    if (t < MAXCHUNK) {
        int v = (t < nchunk) ? g_part[t] : 0;
        s[t] = v;
    }
    __syncthreads();
    if (t < MAXCHUNK) {
        #pragma unroll
        for (int off = 1; off < MAXCHUNK; off <<= 1) {
            int add = (t >= off) ? s[t - off] : 0;
            __syncthreads();
            s[t] += add;
            __syncthreads();
        }
        // s[t] is inclusive; convert on read below
    } else {
        #pragma unroll
        for (int off = 1; off < MAXCHUNK; off <<= 1) { __syncthreads(); __syncthreads(); }
    }
    __syncthreads();
    int i = blockIdx.x * blockDim.x + t;
    if (i < n) {
        int c = i >> 10;
        int base = (c == 0) ? 0 : s[c - 1];     // exclusive chunk offset
        int rp = g_rowptr[i] + base;
        g_rowptr[i] = rp;
        g_cursor[i] = rp;
        g_nsrc[i] = rsqrtf((float)max(g_degout[i], 1));
        g_ndst[i] = rsqrtf((float)max(g_degin[i], 1));
    }
    if (i == 0) g_rowptr[n] = E;
}

__global__ void k_fill(const int* __restrict__ src, const int* __restrict__ dst, int E) {
    int e = blockIdx.x * blockDim.x + threadIdx.x;
    if (e < E) {
        int p = atomicAdd(&g_cursor[dst[e]], 1);
        g_col[p] = src[e];
    }
}

// ---------------------------------------------------------------- GEMM (f32x2, row-pair)
// x[n,128] = (A[n,128] * nsrc[n]) @ W[128,128]
// Block 256 thr -> 128 rows. Warp w: rows w*16..w*16+15 as 8 row-pairs.
// Lane: cols lane*4..lane*4+3. acc[8][4] u64 = {row 2p, row 2p+1} at col q.
// smem: Ws2[16][128] u64 dup-pairs (16KB) + As_t[16][132] transposed (8.25KB).
#define KC 16
#define AST 132
__global__ __launch_bounds__(256) void k_gemm(const float* __restrict__ A,
                                              int n, int useH, int layer) {
    __shared__ u64   Ws2[KC * 128];
    __shared__ float As[KC * AST];
    if (useH) A = g_h;

    int t    = threadIdx.x;
    int lane = t & 31;
    int w    = t >> 5;              // warp: rows [w*16, w*16+16)
    int row0 = blockIdx.x * 128;

    u64 acc[8][4];
    #pragma unroll
    for (int p = 0; p < 8; p++)
        #pragma unroll
        for (int q = 0; q < 4; q++) acc[p][q] = 0ull;

    const float4* Av = (const float4*)A;
    const ulonglong2* Wg = (const ulonglong2*)g_W2[layer];

    for (int kc = 0; kc < 8; kc++) {
        __syncthreads();
        // stage duplicated W chunk: rows [kc*16, kc*16+16) -> 2048 u64 = 1024 u64x2
        #pragma unroll
        for (int i = 0; i < 4; i++) {
            int j = t + i * 256;
            ((ulonglong2*)Ws2)[j] = Wg[kc * 1024 + j];
        }
        // stage A tile transposed: 128 rows x 16 k -> As[k][r]
        #pragma unroll
        for (int i = 0; i < 2; i++) {
            int j = t + i * 256;            // 512 float4: r = j>>2, c = j&3
            int r = j >> 2, c = j & 3;
            int gr = row0 + r;
            float4 v = make_float4(0.f, 0.f, 0.f, 0.f);
            if (gr < n) {
                float ns = g_nsrc[gr];
                v = Av[gr * 32 + kc * 4 + c];
                v.x *= ns; v.y *= ns; v.z *= ns; v.w *= ns;
            }
            As[(c * 4 + 0) * AST + r] = v.x;
            As[(c * 4 + 1) * AST + r] = v.y;
            As[(c * 4 + 2) * AST + r] = v.z;
            As[(c * 4 + 3) * AST + r] = v.w;
        }
        __syncthreads();

        #pragma unroll
        for (int kk = 0; kk < KC; kk++) {
            // broadcast 16 row values (8 pairs) for this warp — 4 LDS.128
            u64 ap[8];
            #pragma unroll
            for (int i = 0; i < 4; i++) {
                float4 a4 = *(const float4*)&As[kk * AST + w * 16 + i * 4];
                ap[i * 2 + 0] = *(u64*)&a4.x;   // {r0, r1}
                ap[i * 2 + 1] = *(u64*)&a4.z;   // {r2, r3}
            }
            // duplicated w for lane's 4 cols — 2 LDS.128
            ulonglong2 w01 = *(const ulonglong2*)&Ws2[kk * 128 + lane * 4];
            ulonglong2 w23 = *(const ulonglong2*)&Ws2[kk * 128 + lane * 4 + 2];
            #pragma unroll
            for (int p = 0; p < 8; p++) {
                acc[p][0] = fma2(ap[p], w01.x, acc[p][0]);
                acc[p][1] = fma2(ap[p], w01.y, acc[p][1]);
                acc[p][2] = fma2(ap[p], w23.x, acc[p][2]);
                acc[p][3] = fma2(ap[p], w23.y, acc[p][3]);
            }
        }
    }

    // epilogue: unpack row-pairs
    #pragma unroll
    for (int p = 0; p < 8; p++) {
        int r0 = row0 + w * 16 + p * 2;
        float2 c0 = *(float2*)&acc[p][0];
        float2 c1 = *(float2*)&acc[p][1];
        float2 c2 = *(float2*)&acc[p][2];
        float2 c3 = *(float2*)&acc[p][3];
        if (r0 < n)
            *(float4*)&g_x[r0 * 128 + lane * 4] = make_float4(c0.x, c1.x, c2.x, c3.x);
        if (r0 + 1 < n)
            *(float4*)&g_x[(r0 + 1) * 128 + lane * 4] = make_float4(c0.y, c1.y, c2.y, c3.y);
    }
}

// ---------------------------------------------------------------- aggregation
__global__ __launch_bounds__(256) void k_agg(const float* __restrict__ bias,
                                             float* __restrict__ outp,
                                             int n, int relu, int toH) {
    int gw   = (blockIdx.x * blockDim.x + threadIdx.x) >> 5;
    int lane = threadIdx.x & 31;
    if (gw >= n) return;

    int beg = g_rowptr[gw];
    int end = g_rowptr[gw + 1];
    const float4* x4 = (const float4*)g_x;

    float4 acc = make_float4(0.f, 0.f, 0.f, 0.f);
    int j = beg;
    for (; j + 4 <= end; j += 4) {
        int s0 = g_col[j],     s1 = g_col[j + 1];
        int s2 = g_col[j + 2], s3 = g_col[j + 3];
        float4 v0 = __ldg(x4 + s0 * 32 + lane);
        float4 v1 = __ldg(x4 + s1 * 32 + lane);
        float4 v2 = __ldg(x4 + s2 * 32 + lane);
        float4 v3 = __ldg(x4 + s3 * 32 + lane);
        acc.x += (v0.x + v1.x) + (v2.x + v3.x);
        acc.y += (v0.y + v1.y) + (v2.y + v3.y);
        acc.z += (v0.z + v1.z) + (v2.z + v3.z);
        acc.w += (v0.w + v1.w) + (v2.w + v3.w);
    }
    for (; j < end; j++) {
        int s = g_col[j];
        float4 v = __ldg(x4 + s * 32 + lane);
        acc.x += v.x; acc.y += v.y; acc.z += v.z; acc.w += v.w;
    }

    float nd = g_ndst[gw];
    float4 b = __ldg((const float4*)bias + lane);
    float4 o;
    o.x = acc.x * nd + b.x;
    o.y = acc.y * nd + b.y;
    o.z = acc.z * nd + b.z;
    o.w = acc.w * nd + b.w;
    if (relu) {
        o.x = fmaxf(o.x, 0.f); o.y = fmaxf(o.y, 0.f);
        o.z = fmaxf(o.z, 0.f); o.w = fmaxf(o.w, 0.f);
    }
    float4* dst4 = toH ? (float4*)g_h : (float4*)outp;
    dst4[gw * 32 + lane] = o;
}

// ---------------------------------------------------------------- launch
extern "C" void kernel_launch(void* const* d_in, const int* in_sizes, int n_in,
                              void* d_out, int out_size) {
    const float* feature = (const float*)d_in[0];
    const int*   src     = (const int*)d_in[1];
    const int*   dst     = (const int*)d_in[2];
    const float* W1      = (const float*)d_in[3];
    const float* b1      = (const float*)d_in[4];
    const float* W2      = (const float*)d_in[5];
    const float* b2      = (const float*)d_in[6];
    float* out = (float*)d_out;

    int N = in_sizes[0] / 128;
    int E = in_sizes[1];
    int nchunk = (N + SCAN_CHUNK - 1) / SCAN_CHUNK;

    // graph preprocessing + weight duplication
    k_zero<<<(N + 255) / 256, 256>>>(N);
    k_dupw<<<64, 256>>>(W1, W2);
    k_deg<<<(E + 255) / 256, 256>>>(src, dst, E);
    k_scan1<<<nchunk, SCAN_CHUNK>>>(N);
    k_scanfin<<<(N + 1023) / 1024, 1024>>>(N, E, nchunk);
    k_fill<<<(E + 255) / 256, 256>>>(src, dst, E);

    int gemm_grid = (N + 127) / 128;
    int agg_grid  = (N * 32 + 255) / 256;

    // layer 0: relu -> g_h
    k_gemm<<<gemm_grid, 256>>>(feature, N, 0, 0);
    k_agg<<<agg_grid, 256>>>(b1, out, N, 1, 1);

    // layer 1: no activation -> d_out
    k_gemm<<<gemm_grid, 256>>>(nullptr, N, 1, 1);
    k_agg<<<agg_grid, 256>>>(b2, out, N, 0, 0);
}

// round 9
// speedup vs baseline: 1.0372x; 1.0372x over previous
#include <cuda_runtime.h>
#include <cuda_bf16.h>

// GNN_30064771072959: 2-layer GCN (DGL GraphConv, norm='both')
// R9: R7 GEMM skeleton + duplicated-A smem (kills all inner-loop splat MOVs).
//     W staged plain (no doubled L2 stream — R8's mistake). Launch order puts
//     k_gemm at position 6 so ncu -s5 -c1 samples it.

#define MAXN 131072
#define MAXE 1700000
#define SCAN_CHUNK 1024
#define MAXCHUNK (MAXN / SCAN_CHUNK)   // 128

typedef unsigned long long u64;

__device__ float g_x[MAXN * 128];      // GEMM output (gather source)
__device__ float g_h[MAXN * 128];      // layer-1 hidden
__device__ int   g_col[MAXE];          // CSR col (= src) by dst
__device__ int   g_rowptr[MAXN + 1];
__device__ int   g_cursor[MAXN];
__device__ int   g_degout[MAXN];
__device__ int   g_degin[MAXN];
__device__ float g_nsrc[MAXN];
__device__ float g_ndst[MAXN];
__device__ int   g_part[MAXCHUNK];

__device__ __forceinline__ u64 fma2(u64 a, u64 b, u64 c) {
    u64 d;
    asm("fma.rn.f32x2 %0, %1, %2, %3;" : "=l"(d) : "l"(a), "l"(b), "l"(c));
    return d;
}
__device__ __forceinline__ u64 dup2(float a) {
    u64 d;
    asm("mov.b64 %0, {%1, %1};" : "=l"(d) : "f"(a));
    return d;
}

// ---------------------------------------------------------------- degrees
__global__ void k_zero(int n) {
    int i = blockIdx.x * blockDim.x + threadIdx.x;
    if (i < n) { g_degout[i] = 0; g_degin[i] = 0; }
}

__global__ void k_deg(const int* __restrict__ src, const int* __restrict__ dst, int E) {
    int e = blockIdx.x * blockDim.x + threadIdx.x;
    if (e < E) {
        atomicAdd(&g_degout[src[e]], 1);
        atomicAdd(&g_degin[dst[e]], 1);
    }
}

// ---------------------------------------------------------------- scan (rowptr)
__global__ void k_scan1(int n) {
    __shared__ int s[SCAN_CHUNK];
    int t = threadIdx.x;
    int i = blockIdx.x * SCAN_CHUNK + t;
    int v = (i < n) ? g_degin[i] : 0;
    s[t] = v;
    __syncthreads();
    #pragma unroll
    for (int off = 1; off < SCAN_CHUNK; off <<= 1) {
        int add = (t >= off) ? s[t - off] : 0;
        __syncthreads();
        s[t] += add;
        __syncthreads();
    }
    if (i < n) g_rowptr[i] = s[t] - v;          // local exclusive
    if (t == SCAN_CHUNK - 1) g_part[blockIdx.x] = s[t];
}

// finalize: every block redundantly scans the (<=128) chunk partials in smem,
// then computes rowptr/cursor/norms.
__global__ void k_scanfin(int n, int E, int nchunk) {
    __shared__ int s[MAXCHUNK];
    int t = threadIdx.x;
    if (t < MAXCHUNK) {
        int v = (t < nchunk) ? g_part[t] : 0;
        s[t] = v;
    }
    __syncthreads();
    if (t < MAXCHUNK) {
        #pragma unroll
        for (int off = 1; off < MAXCHUNK; off <<= 1) {
            int add = (t >= off) ? s[t - off] : 0;
            __syncthreads();
            s[t] += add;
            __syncthreads();
        }
    } else {
        #pragma unroll
        for (int off = 1; off < MAXCHUNK; off <<= 1) { __syncthreads(); __syncthreads(); }
    }
    __syncthreads();
    int i = blockIdx.x * blockDim.x + t;
    if (i < n) {
        int c = i >> 10;
        int base = (c == 0) ? 0 : s[c - 1];     // exclusive chunk offset
        int rp = g_rowptr[i] + base;
        g_rowptr[i] = rp;
        g_cursor[i] = rp;
        g_nsrc[i] = rsqrtf((float)max(g_degout[i], 1));
        g_ndst[i] = rsqrtf((float)max(g_degin[i], 1));
    }
    if (i == 0) g_rowptr[n] = E;
}

__global__ void k_fill(const int* __restrict__ src, const int* __restrict__ dst, int E) {
    int e = blockIdx.x * blockDim.x + threadIdx.x;
    if (e < E) {
        int p = atomicAdd(&g_cursor[dst[e]], 1);
        g_col[p] = src[e];
    }
}

// ---------------------------------------------------------------- GEMM (f32x2, dup-A)
// x[n,128] = (A[n,128] * nsrc[n]) @ W[128,128]
// Block: 256 thr -> 64 rows x 128 cols. Warp w owns rows w*8..w*8+7 (a-loads
// are smem BROADCASTS of pre-duplicated {a,a} u64s); lane owns cols
// lane*4..lane*4+3 as two f32x2 accums. Inner loop has ZERO MOVs.
// smem: Ws[32][128] plain (16KB) + AsD[64][34] u64 dup, pad-2 (17KB).
#define ADS 34
__global__ __launch_bounds__(256) void k_gemm(const float* __restrict__ A,
                                              const float* __restrict__ W,
                                              int n, int useH) {
    __shared__ float Ws[32 * 128];
    __shared__ u64   AsD[64 * ADS];
    if (useH) A = g_h;

    int t    = threadIdx.x;
    int lane = t & 31;
    int w    = t >> 5;          // warp id: rows [w*8, w*8+8)
    int row0 = blockIdx.x * 64;

    u64 acc[8][2];
    #pragma unroll
    for (int i = 0; i < 8; i++) { acc[i][0] = 0ull; acc[i][1] = 0ull; }

    const float4* Av = (const float4*)A;

    for (int kc = 0; kc < 128; kc += 32) {
        __syncthreads();
        // stage W rows [kc, kc+32): 4096 floats, coalesced float4
        #pragma unroll
        for (int i = 0; i < 4; i++) {
            int idx4 = t + i * 256;
            ((float4*)Ws)[idx4] = ((const float4*)W)[kc * 32 + idx4];
        }
        // stage scaled, DUPLICATED A tile: 64 rows x 32 k as {a,a} u64
        #pragma unroll
        for (int i = 0; i < 2; i++) {
            int j = t + i * 256;            // 512 float4 = 64 rows x 8 chunks
            int r = j >> 3, c = j & 7;
            int gr = row0 + r;
            float4 v = make_float4(0.f, 0.f, 0.f, 0.f);
            if (gr < n) {
                float ns = g_nsrc[gr];
                v = Av[gr * 32 + (kc >> 2) + c];
                v.x *= ns; v.y *= ns; v.z *= ns; v.w *= ns;
            }
            ulonglong2* dstp = (ulonglong2*)&AsD[r * ADS + c * 4];
            dstp[0] = make_ulonglong2(dup2(v.x), dup2(v.y));
            dstp[1] = make_ulonglong2(dup2(v.z), dup2(v.w));
        }
        __syncthreads();

        #pragma unroll
        for (int kk = 0; kk < 32; kk += 2) {
            // broadcast duplicated a-pairs for this warp's 8 rows (2 k-steps each)
            ulonglong2 aD[8];
            #pragma unroll
            for (int i = 0; i < 8; i++)
                aD[i] = *(const ulonglong2*)&AsD[(w * 8 + i) * ADS + kk];

            float4 wv0 = *(const float4*)&Ws[kk * 128 + lane * 4];
            float4 wv1 = *(const float4*)&Ws[(kk + 1) * 128 + lane * 4];
            u64 w0a = *(u64*)&wv0.x, w0b = *(u64*)&wv0.z;   // register aliasing, no MOV
            u64 w1a = *(u64*)&wv1.x, w1b = *(u64*)&wv1.z;

            #pragma unroll
            for (int i = 0; i < 8; i++) {
                acc[i][0] = fma2(aD[i].x, w0a, acc[i][0]);
                acc[i][1] = fma2(aD[i].x, w0b, acc[i][1]);
                acc[i][0] = fma2(aD[i].y, w1a, acc[i][0]);
                acc[i][1] = fma2(aD[i].y, w1b, acc[i][1]);
            }
        }
    }

    #pragma unroll
    for (int i = 0; i < 8; i++) {
        int gr = row0 + w * 8 + i;
        if (gr < n) {
            float2 lo = *(float2*)&acc[i][0];
            float2 hi = *(float2*)&acc[i][1];
            *(float4*)&g_x[gr * 128 + lane * 4] = make_float4(lo.x, lo.y, hi.x, hi.y);
        }
    }
}

// ---------------------------------------------------------------- aggregation
// warp per node; lane owns 4 cols (float4). 4-edge unroll for MLP.
__global__ __launch_bounds__(256) void k_agg(const float* __restrict__ bias,
                                             float* __restrict__ outp,
                                             int n, int relu, int toH) {
    int gw   = (blockIdx.x * blockDim.x + threadIdx.x) >> 5;
    int lane = threadIdx.x & 31;
    if (gw >= n) return;

    int beg = g_rowptr[gw];
    int end = g_rowptr[gw + 1];
    const float4* x4 = (const float4*)g_x;

    float4 acc = make_float4(0.f, 0.f, 0.f, 0.f);
    int j = beg;
    for (; j + 4 <= end; j += 4) {
        int s0 = g_col[j],     s1 = g_col[j + 1];
        int s2 = g_col[j + 2], s3 = g_col[j + 3];
        float4 v0 = __ldg(x4 + s0 * 32 + lane);
        float4 v1 = __ldg(x4 + s1 * 32 + lane);
        float4 v2 = __ldg(x4 + s2 * 32 + lane);
        float4 v3 = __ldg(x4 + s3 * 32 + lane);
        acc.x += (v0.x + v1.x) + (v2.x + v3.x);
        acc.y += (v0.y + v1.y) + (v2.y + v3.y);
        acc.z += (v0.z + v1.z) + (v2.z + v3.z);
        acc.w += (v0.w + v1.w) + (v2.w + v3.w);
    }
    for (; j < end; j++) {
        int s = g_col[j];
        float4 v = __ldg(x4 + s * 32 + lane);
        acc.x += v.x; acc.y += v.y; acc.z += v.z; acc.w += v.w;
    }

    float nd = g_ndst[gw];
    float4 b = __ldg((const float4*)bias + lane);
    float4 o;
    o.x = acc.x * nd + b.x;
    o.y = acc.y * nd + b.y;
    o.z = acc.z * nd + b.z;
    o.w = acc.w * nd + b.w;
    if (relu) {
        o.x = fmaxf(o.x, 0.f); o.y = fmaxf(o.y, 0.f);
        o.z = fmaxf(o.z, 0.f); o.w = fmaxf(o.w, 0.f);
    }
    float4* dst4 = toH ? (float4*)g_h : (float4*)outp;
    dst4[gw * 32 + lane] = o;
}

// ---------------------------------------------------------------- launch
extern "C" void kernel_launch(void* const* d_in, const int* in_sizes, int n_in,
                              void* d_out, int out_size) {
    const float* feature = (const float*)d_in[0];
    const int*   src     = (const int*)d_in[1];
    const int*   dst     = (const int*)d_in[2];
    const float* W1      = (const float*)d_in[3];
    const float* b1      = (const float*)d_in[4];
    const float* W2      = (const float*)d_in[5];
    const float* b2      = (const float*)d_in[6];
    float* out = (float*)d_out;

    int N = in_sizes[0] / 128;
    int E = in_sizes[1];
    int nchunk = (N + SCAN_CHUNK - 1) / SCAN_CHUNK;

    // graph preprocessing (5 launches -> ncu -s5 samples k_gemm next)
    k_zero<<<(N + 255) / 256, 256>>>(N);
    k_deg<<<(E + 255) / 256, 256>>>(src, dst, E);
    k_scan1<<<nchunk, SCAN_CHUNK>>>(N);
    k_scanfin<<<(N + 1023) / 1024, 1024>>>(N, E, nchunk);
    k_fill<<<(E + 255) / 256, 256>>>(src, dst, E);

    int gemm_grid = (N + 63) / 64;
    int agg_grid  = (N * 32 + 255) / 256;

    // layer 0: relu -> g_h
    k_gemm<<<gemm_grid, 256>>>(feature, W1, N, 0);
    k_agg<<<agg_grid, 256>>>(b1, out, N, 1, 1);

    // layer 1: no activation -> d_out
    k_gemm<<<gemm_grid, 256>>>(nullptr, W2, N, 1);
    k_agg<<<agg_grid, 256>>>(b2, out, N, 0, 0);
}

// round 10
// speedup vs baseline: 1.1145x; 1.0745x over previous
#include <cuda_runtime.h>
#include <cuda_bf16.h>

// GNN_30064771072959: 2-layer GCN (DGL GraphConv, norm='both')
// R10: revert to R7 GEMM exactly (best: 297us). Reorder launches so k_gemm is
//      the 4th launch (the one ncu captures). k_agg unroll 4->8 edges.

#define MAXN 131072
#define MAXE 1700000
#define SCAN_CHUNK 1024
#define MAXCHUNK (MAXN / SCAN_CHUNK)   // 128

typedef unsigned long long u64;

__device__ float g_x[MAXN * 128];      // GEMM output (gather source)
__device__ float g_h[MAXN * 128];      // layer-1 hidden
__device__ int   g_col[MAXE];          // CSR col (= src) by dst
__device__ int   g_rowptr[MAXN + 1];
__device__ int   g_cursor[MAXN];
__device__ int   g_degout[MAXN];
__device__ int   g_degin[MAXN];
__device__ float g_nsrc[MAXN];
__device__ float g_ndst[MAXN];
__device__ int   g_part[MAXCHUNK];

__device__ __forceinline__ u64 fma2(u64 a, u64 b, u64 c) {
    u64 d;
    asm("fma.rn.f32x2 %0, %1, %2, %3;" : "=l"(d) : "l"(a), "l"(b), "l"(c));
    return d;
}
__device__ __forceinline__ u64 splat2(float a) {
    u64 d;
    asm("mov.b64 %0, {%1, %1};" : "=l"(d) : "f"(a));
    return d;
}

// ---------------------------------------------------------------- degrees
__global__ void k_zero(int n) {
    int i = blockIdx.x * blockDim.x + threadIdx.x;
    if (i < n) { g_degout[i] = 0; g_degin[i] = 0; }
}

__global__ void k_deg(const int* __restrict__ src, const int* __restrict__ dst, int E) {
    int e = blockIdx.x * blockDim.x + threadIdx.x;
    if (e < E) {
        atomicAdd(&g_degout[src[e]], 1);
        atomicAdd(&g_degin[dst[e]], 1);
    }
}

__global__ void k_norm(int n) {
    int i = blockIdx.x * blockDim.x + threadIdx.x;
    if (i < n) {
        g_nsrc[i] = rsqrtf((float)max(g_degout[i], 1));
        g_ndst[i] = rsqrtf((float)max(g_degin[i], 1));
    }
}

// ---------------------------------------------------------------- scan (rowptr)
__global__ void k_scan1(int n) {
    __shared__ int s[SCAN_CHUNK];
    int t = threadIdx.x;
    int i = blockIdx.x * SCAN_CHUNK + t;
    int v = (i < n) ? g_degin[i] : 0;
    s[t] = v;
    __syncthreads();
    #pragma unroll
    for (int off = 1; off < SCAN_CHUNK; off <<= 1) {
        int add = (t >= off) ? s[t - off] : 0;
        __syncthreads();
        s[t] += add;
        __syncthreads();
    }
    if (i < n) g_rowptr[i] = s[t] - v;          // local exclusive
    if (t == SCAN_CHUNK - 1) g_part[blockIdx.x] = s[t];
}

// finalize: every block redundantly scans the (<=128) chunk partials in smem,
// then computes rowptr/cursor.
__global__ void k_scanfin(int n, int E, int nchunk) {
    __shared__ int s[MAXCHUNK];
    int t = threadIdx.x;
    if (t < MAXCHUNK) {
        int v = (t < nchunk) ? g_part[t] : 0;
        s[t] = v;
    }
    __syncthreads();
    if (t < MAXCHUNK) {
        #pragma unroll
        for (int off = 1; off < MAXCHUNK; off <<= 1) {
            int add = (t >= off) ? s[t - off] : 0;
            __syncthreads();
            s[t] += add;
            __syncthreads();
        }
    } else {
        #pragma unroll
        for (int off = 1; off < MAXCHUNK; off <<= 1) { __syncthreads(); __syncthreads(); }
    }
    __syncthreads();
    int i = blockIdx.x * blockDim.x + t;
    if (i < n) {
        int c = i >> 10;
        int base = (c == 0) ? 0 : s[c - 1];     // exclusive chunk offset
        int rp = g_rowptr[i] + base;
        g_rowptr[i] = rp;
        g_cursor[i] = rp;
    }
    if (i == 0) g_rowptr[n] = E;
}

__global__ void k_fill(const int* __restrict__ src, const int* __restrict__ dst, int E) {
    int e = blockIdx.x * blockDim.x + threadIdx.x;
    if (e < E) {
        int p = atomicAdd(&g_cursor[dst[e]], 1);
        g_col[p] = src[e];
    }
}

// ---------------------------------------------------------------- GEMM (f32x2) — R7 version
// x[n,128] = (A[n,128] * nsrc[n]) @ W[128,128]
// Block: 256 thr -> 64 rows x 128 cols. Warp w owns rows w*8..w*8+7 (a-loads
// are smem BROADCASTS); lane owns cols lane*4..lane*4+3 as two f32x2 accums.
// smem: Ws[32][128] (16KB) + As[64][34] pad-2 (8.5KB).
#define AS_STRIDE 34
__global__ __launch_bounds__(256) void k_gemm(const float* __restrict__ A,
                                              const float* __restrict__ W,
                                              int n, int useH) {
    __shared__ float Ws[32 * 128];
    __shared__ float As[64 * AS_STRIDE];
    if (useH) A = g_h;

    int t    = threadIdx.x;
    int lane = t & 31;
    int w    = t >> 5;          // warp id: rows [w*8, w*8+8)
    int row0 = blockIdx.x * 64;

    u64 acc[8][2];
    #pragma unroll
    for (int i = 0; i < 8; i++) { acc[i][0] = 0ull; acc[i][1] = 0ull; }

    const float4* Av = (const float4*)A;

    for (int kc = 0; kc < 128; kc += 32) {
        __syncthreads();
        // load W rows [kc, kc+32): 4096 floats, coalesced float4
        #pragma unroll
        for (int i = 0; i < 4; i++) {
            int idx4 = t + i * 256;
            ((float4*)Ws)[idx4] = ((const float4*)W)[kc * 32 + idx4];
        }
        // load scaled A tile 64x32 (row-major, stride AS_STRIDE)
        #pragma unroll
        for (int i = 0; i < 2; i++) {
            int j = t + i * 256;            // 512 float4 = 64 rows x 8 chunks
            int r = j >> 3, c = j & 7;
            int gr = row0 + r;
            float4 v = make_float4(0.f, 0.f, 0.f, 0.f);
            if (gr < n) {
                float ns = g_nsrc[gr];
                v = Av[gr * 32 + (kc >> 2) + c];
                v.x *= ns; v.y *= ns; v.z *= ns; v.w *= ns;
            }
            int base = r * AS_STRIDE + c * 4;
            As[base + 0] = v.x; As[base + 1] = v.y;
            As[base + 2] = v.z; As[base + 3] = v.w;
        }
        __syncthreads();

        #pragma unroll
        for (int kk = 0; kk < 32; kk += 2) {
            // broadcast a-pairs (2 k-steps) for this warp's 8 rows
            float2 a2[8];
            #pragma unroll
            for (int i = 0; i < 8; i++)
                a2[i] = *(const float2*)&As[(w * 8 + i) * AS_STRIDE + kk];

            #pragma unroll
            for (int sub = 0; sub < 2; sub++) {
                float4 wv = *(const float4*)&Ws[(kk + sub) * 128 + lane * 4];
                u64 w01, w23;
                asm("mov.b64 %0, {%1, %2};" : "=l"(w01) : "f"(wv.x), "f"(wv.y));
                asm("mov.b64 %0, {%1, %2};" : "=l"(w23) : "f"(wv.z), "f"(wv.w));
                #pragma unroll
                for (int i = 0; i < 8; i++) {
                    u64 as = splat2(sub ? a2[i].y : a2[i].x);
                    acc[i][0] = fma2(as, w01, acc[i][0]);
                    acc[i][1] = fma2(as, w23, acc[i][1]);
                }
            }
        }
    }

    #pragma unroll
    for (int i = 0; i < 8; i++) {
        int gr = row0 + w * 8 + i;
        if (gr < n) {
            float2 lo = *(float2*)&acc[i][0];
            float2 hi = *(float2*)&acc[i][1];
            *(float4*)&g_x[gr * 128 + lane * 4] = make_float4(lo.x, lo.y, hi.x, hi.y);
        }
    }
}

// ---------------------------------------------------------------- aggregation
// warp per node; lane owns 4 cols (float4). 8-edge unroll for MLP.
__global__ __launch_bounds__(256) void k_agg(const float* __restrict__ bias,
                                             float* __restrict__ outp,
                                             int n, int relu, int toH) {
    int gw   = (blockIdx.x * blockDim.x + threadIdx.x) >> 5;
    int lane = threadIdx.x & 31;
    if (gw >= n) return;

    int beg = g_rowptr[gw];
    int end = g_rowptr[gw + 1];
    const float4* x4 = (const float4*)g_x;

    float4 acc = make_float4(0.f, 0.f, 0.f, 0.f);
    int j = beg;
    for (; j + 8 <= end; j += 8) {
        int s0 = g_col[j],     s1 = g_col[j + 1];
        int s2 = g_col[j + 2], s3 = g_col[j + 3];
        int s4 = g_col[j + 4], s5 = g_col[j + 5];
        int s6 = g_col[j + 6], s7 = g_col[j + 7];
        float4 v0 = __ldg(x4 + s0 * 32 + lane);
        float4 v1 = __ldg(x4 + s1 * 32 + lane);
        float4 v2 = __ldg(x4 + s2 * 32 + lane);
        float4 v3 = __ldg(x4 + s3 * 32 + lane);
        float4 v4 = __ldg(x4 + s4 * 32 + lane);
        float4 v5 = __ldg(x4 + s5 * 32 + lane);
        float4 v6 = __ldg(x4 + s6 * 32 + lane);
        float4 v7 = __ldg(x4 + s7 * 32 + lane);
        acc.x += ((v0.x + v1.x) + (v2.x + v3.x)) + ((v4.x + v5.x) + (v6.x + v7.x));
        acc.y += ((v0.y + v1.y) + (v2.y + v3.y)) + ((v4.y + v5.y) + (v6.y + v7.y));
        acc.z += ((v0.z + v1.z) + (v2.z + v3.z)) + ((v4.z + v5.z) + (v6.z + v7.z));
        acc.w += ((v0.w + v1.w) + (v2.w + v3.w)) + ((v4.w + v5.w) + (v6.w + v7.w));
    }
    for (; j < end; j++) {
        int s = g_col[j];
        float4 v = __ldg(x4 + s * 32 + lane);
        acc.x += v.x; acc.y += v.y; acc.z += v.z; acc.w += v.w;
    }

    float nd = g_ndst[gw];
    float4 b = __ldg((const float4*)bias + lane);
    float4 o;
    o.x = acc.x * nd + b.x;
    o.y = acc.y * nd + b.y;
    o.z = acc.z * nd + b.z;
    o.w = acc.w * nd + b.w;
    if (relu) {
        o.x = fmaxf(o.x, 0.f); o.y = fmaxf(o.y, 0.f);
        o.z = fmaxf(o.z, 0.f); o.w = fmaxf(o.w, 0.f);
    }
    float4* dst4 = toH ? (float4*)g_h : (float4*)outp;
    dst4[gw * 32 + lane] = o;
}

// ---------------------------------------------------------------- launch
extern "C" void kernel_launch(void* const* d_in, const int* in_sizes, int n_in,
                              void* d_out, int out_size) {
    const float* feature = (const float*)d_in[0];
    const int*   src     = (const int*)d_in[1];
    const int*   dst     = (const int*)d_in[2];
    const float* W1      = (const float*)d_in[3];
    const float* b1      = (const float*)d_in[4];
    const float* W2      = (const float*)d_in[5];
    const float* b2      = (const float*)d_in[6];
    float* out = (float*)d_out;

    int N = in_sizes[0] / 128;
    int E = in_sizes[1];
    int nchunk = (N + SCAN_CHUNK - 1) / SCAN_CHUNK;

    int gemm_grid = (N + 63) / 64;
    int agg_grid  = (N * 32 + 255) / 256;

    // launches 1-3: degrees + norms (all gemm0 needs besides inputs)
    k_zero<<<(N + 255) / 256, 256>>>(N);
    k_deg<<<(E + 255) / 256, 256>>>(src, dst, E);
    k_norm<<<(N + 255) / 256, 256>>>(N);

    // launch 4 (ncu-profiled): layer-0 GEMM
    k_gemm<<<gemm_grid, 256>>>(feature, W1, N, 0);

    // CSR build (needed only by k_agg)
    k_scan1<<<nchunk, SCAN_CHUNK>>>(N);
    k_scanfin<<<(N + 1023) / 1024, 1024>>>(N, E, nchunk);
    k_fill<<<(E + 255) / 256, 256>>>(src, dst, E);

    // layer 0 aggregation: relu -> g_h
    k_agg<<<agg_grid, 256>>>(b1, out, N, 1, 1);

    // layer 1: no activation -> d_out
    k_gemm<<<gemm_grid, 256>>>(nullptr, W2, N, 1);
    k_agg<<<agg_grid, 256>>>(b2, out, N, 0, 0);
}